// round 16
// baseline (speedup 1.0000x reference)
#include <cuda_runtime.h>
#include <cuda_bf16.h>
#include <math.h>

#define Bsz   512
#define Tsz   256
#define Fsz   128
#define Hsz   512
#define FFsz  1024
#define OUTsz 64
#define H3    (3 * Hsz)
#define BT    (Bsz * Tsz)
#define PADV  (-999.0f)
#define GW_WORDS 24576   // per-block_n W slice (bf16): 32kt*3g*2nw*(32lane*4w) = 96KB

// ---------------- scratch ----------------
__device__ float g_GI[(size_t)BT * H3];
__device__ float g_ffin[(size_t)BT * Hsz];
__device__ float g_hid[(size_t)BT * FFsz];
// fragment-major h (bf16x2 words, kp-paired): [pp][m][kp(16)][16 words]
__device__ unsigned g_hfrag[2][(size_t)Bsz * 256];
__device__ unsigned g_wfrag[16 * GW_WORDS];
__device__ unsigned g_barg[8 * 32];   // per-m-group barrier counters (128B spaced)

// ---------------- helpers ----------------
__device__ __forceinline__ unsigned long long pack2(float x, float y) {
    unsigned long long r;
    asm("mov.b64 %0,{%1,%2};" : "=l"(r) : "f"(x), "f"(y));
    return r;
}
__device__ __forceinline__ void fma2(unsigned long long& d, unsigned long long a,
                                     unsigned long long b) {
    asm("fma.rn.f32x2 %0,%1,%2,%0;" : "+l"(d) : "l"(a), "l"(b));
}
__device__ __forceinline__ void unpack2(unsigned long long v, float& x, float& y) {
    asm("mov.b64 {%0,%1},%2;" : "=f"(x), "=f"(y) : "l"(v));
}
__device__ __forceinline__ void mma_bf16(float* d, unsigned a0, unsigned a1,
                                         unsigned a2, unsigned a3,
                                         unsigned b0, unsigned b1) {
    asm volatile(
        "mma.sync.aligned.m16n8k16.row.col.f32.bf16.bf16.f32 "
        "{%0,%1,%2,%3},{%4,%5,%6,%7},{%8,%9},{%0,%1,%2,%3};"
        : "+f"(d[0]), "+f"(d[1]), "+f"(d[2]), "+f"(d[3])
        : "r"(a0), "r"(a1), "r"(a2), "r"(a3), "r"(b0), "r"(b1));
}
__device__ __forceinline__ unsigned bf2pack(float x, float y) {
    __nv_bfloat162 v = __floats2bfloat162_rn(x, y);
    return *(unsigned*)&v;
}

// ---------------- init ----------------
__global__ void init_kernel() {
    int i = blockIdx.x * blockDim.x + threadIdx.x;
    int tot = Bsz * 256;
    if (i < tot) g_hfrag[0][i] = 0u;
    if (i < 8 * 32) g_barg[i] = 0u;
}

// ---------------- W_hh -> bf16 fragment layout ----------------
// [bn(16)][kt(32)][g(3)][nw(2)][lane(32)][4w: j0b0,j0b1,j1b0,j1b1]
__global__ void wprep_kernel(const float* __restrict__ W_hh) {
    int idx = blockIdx.x * blockDim.x + threadIdx.x;
    if (idx >= 16 * 32 * 3 * 2 * 32) return;
    int lane = idx & 31;
    int r = idx >> 5;
    int nw = r & 1; r >>= 1;
    int g = r % 3;  r /= 3;
    int kt = r & 31;
    int bn = r >> 5;
    int grp = lane >> 2, thr = lane & 3;

    unsigned w[4];
#pragma unroll
    for (int j = 0; j < 2; j++) {
        int n_row = g * Hsz + bn * 32 + nw * 16 + j * 8 + grp;
        const float* src = &W_hh[(size_t)n_row * Hsz + kt * 16 + thr * 2];
        w[j * 2 + 0] = bf2pack(src[0], src[1]);
        w[j * 2 + 1] = bf2pack(src[8], src[9]);
    }
    unsigned* dst = &g_wfrag[(size_t)(((bn * 32 + kt) * 3 + g) * 2 + nw) * 128 + lane * 4];
#pragma unroll
    for (int i = 0; i < 4; i++) dst[i] = w[i];
}

// ---------------- plain bf16 MMA GEMM (R13 version; verified) -------------------
template <int KDIM, int NDIM, bool BTRANS, bool RELU, bool SKIP>
__global__ __launch_bounds__(256) void hgemm(const float* __restrict__ A,
                                             const float* __restrict__ Bm,
                                             const float* __restrict__ bias,
                                             float* __restrict__ C,
                                             const int* __restrict__ seq) {
    const int m0 = blockIdx.x * 128;
    const int n0 = blockIdx.y * 128;
    if (SKIP) {
        int b = m0 / Tsz, t0 = m0 % Tsz;
        if (t0 >= seq[b]) return;
    }
    __shared__ __align__(16) unsigned sA[2048];
    __shared__ __align__(16) unsigned sB[2048];

    const int tid = threadIdx.x;
    const int lane = tid & 31;
    const int wid = tid >> 5;
    const int mw = wid >> 2;
    const int nw = wid & 3;
    const int grp = lane >> 2, thr = lane & 3;

    float acc[4][4][4];
#pragma unroll
    for (int i = 0; i < 4; i++)
#pragma unroll
        for (int j = 0; j < 4; j++)
#pragma unroll
            for (int c = 0; c < 4; c++) acc[i][j][c] = 0.0f;

    for (int k0 = 0; k0 < KDIM; k0 += 32) {
        if (k0 > 0) __syncthreads();
#pragma unroll
        for (int it = 0; it < 8; it++) {
            int fid = tid + it * 256;
            int row = fid >> 4, cp = fid & 15;
            int q = cp >> 3, rem = cp & 7;
            int fthr = rem & 3, whalf = rem >> 2;
            int mt = row >> 4, rin = row & 15;
            int fgrp = rin & 7, wlow = rin >> 3;
            int w = whalf * 2 + wlow;
            int flane = fgrp * 4 + fthr;
            float2 v = *(const float2*)&A[(size_t)(m0 + row) * KDIM + k0 + cp * 2];
            sA[(q * 8 + mt) * 128 + flane * 4 + w] = bf2pack(v.x, v.y);
        }
        if (BTRANS) {
#pragma unroll
            for (int it = 0; it < 8; it++) {
                int fid = tid + it * 256;
                int row = fid >> 4, cp = fid & 15;
                int q = cp >> 3, rem = cp & 7;
                int fthr = rem & 3, w = rem >> 2;
                int nt = row >> 3, fgrp = row & 7;
                int flane = fgrp * 4 + fthr;
                float2 v = *(const float2*)&Bm[(size_t)(n0 + row) * KDIM + k0 + cp * 2];
                sB[(q * 16 + nt) * 64 + flane * 2 + w] = bf2pack(v.x, v.y);
            }
        } else {
#pragma unroll
            for (int it = 0; it < 2; it++) {
                int uid = tid + it * 256;
                int kp = uid >> 5, n4 = uid & 31;
                int n = n4 * 4;
                float4 r0 = *(const float4*)&Bm[(size_t)(k0 + kp * 2) * NDIM + n0 + n];
                float4 r1 = *(const float4*)&Bm[(size_t)(k0 + kp * 2 + 1) * NDIM + n0 + n];
                int q = kp >> 3, p = kp & 7;
                int fthr = p & 3, w = p >> 2;
                float e0[4] = {r0.x, r0.y, r0.z, r0.w};
                float e1[4] = {r1.x, r1.y, r1.z, r1.w};
#pragma unroll
                for (int e = 0; e < 4; e++) {
                    int nn = n + e;
                    int nt = nn >> 3, fgrp = nn & 7;
                    int flane = fgrp * 4 + fthr;
                    sB[(q * 16 + nt) * 64 + flane * 2 + w] = bf2pack(e0[e], e1[e]);
                }
            }
        }
        __syncthreads();

#pragma unroll
        for (int q = 0; q < 2; q++) {
            uint2 bb[4];
#pragma unroll
            for (int j = 0; j < 4; j++)
                bb[j] = *(const uint2*)&sB[(q * 16 + nw * 4 + j) * 64 + lane * 2];
#pragma unroll
            for (int i = 0; i < 4; i++) {
                uint4 ah = *(const uint4*)&sA[(q * 8 + mw * 4 + i) * 128 + lane * 4];
#pragma unroll
                for (int j = 0; j < 4; j++)
                    mma_bf16(acc[i][j], ah.x, ah.y, ah.z, ah.w, bb[j].x, bb[j].y);
            }
        }
    }

#pragma unroll
    for (int i = 0; i < 4; i++) {
        const int r0 = m0 + (mw * 4 + i) * 16 + grp;
#pragma unroll
        for (int j = 0; j < 4; j++) {
            const int col = n0 + (nw * 4 + j) * 8 + thr * 2;
            const float b0 = bias[col], b1 = bias[col + 1];
            float o0 = acc[i][j][0] + b0, o1 = acc[i][j][1] + b1;
            float o2 = acc[i][j][2] + b0, o3 = acc[i][j][3] + b1;
            if (RELU) {
                o0 = fmaxf(o0, 0.f); o1 = fmaxf(o1, 0.f);
                o2 = fmaxf(o2, 0.f); o3 = fmaxf(o3, 0.f);
            }
            *(float2*)&C[(size_t)r0 * NDIM + col] = make_float2(o0, o1);
            *(float2*)&C[(size_t)(r0 + 8) * NDIM + col] = make_float2(o2, o3);
        }
    }
}

// ---------------- persistent bf16 tensor-core GRU -------------------------------
// Grid=128. Block: 64 batch x 32 hidden (x3 gates). 96KB W smem. Per kt per warp:
// 6 mma, 3 LDS.128; one LDG.128 per row per kp (2 kts). h fp32 in registers.
__global__ __launch_bounds__(256, 1) void gru_mma(
    const float* __restrict__ GI, const float* __restrict__ b_hh,
    const int* __restrict__ seq, float* __restrict__ ffin) {
    extern __shared__ unsigned Bw[];   // [kt][g][nw][lane*4] = 96KB

    const int tid = threadIdx.x;
    const int lane = tid & 31;
    const int wid  = tid >> 5;
    const int mw = wid & 3, nw = wid >> 2;
    const int grp = lane >> 2, thr = lane & 3;
    const int mgrp = blockIdx.x >> 4;
    const int m0 = mgrp * 64;
    const int block_n = blockIdx.x & 15;
    const int hb = block_n * 32;
    const int kt_g = block_n * 2 + nw;
    const int kp_g = kt_g >> 1, par_g = kt_g & 1;

    // load 96KB W slice into persistent smem
    {
        const uint4* src = (const uint4*)&g_wfrag[(size_t)block_n * GW_WORDS];
        uint4* dst = (uint4*)Bw;
        for (int i = tid; i < GW_WORDS / 4; i += 256) dst[i] = src[i];
    }

    const int m_a = m0 + mw * 16 + grp;
    const int m_b = m_a + 8;
    const int seq_a = seq[m_a];
    const int seq_b = seq[m_b];

    float2 bh[2][3];
#pragma unroll
    for (int j = 0; j < 2; j++) {
        const int hcol = hb + nw * 16 + j * 8 + thr * 2;
#pragma unroll
        for (int g = 0; g < 3; g++) bh[j][g] = *(const float2*)&b_hh[g * Hsz + hcol];
    }

    float hreg[2][2][2];   // [half][j][pair]
#pragma unroll
    for (int a = 0; a < 2; a++)
#pragma unroll
        for (int b = 0; b < 2; b++) { hreg[a][b][0] = 0.0f; hreg[a][b][1] = 0.0f; }

    __syncthreads();

    for (int t = 0; t < Tsz; ++t) {
        const int pp = t & 1;
        const unsigned* __restrict__ Af = g_hfrag[pp];
        unsigned* __restrict__ Ao = g_hfrag[pp ^ 1];

        // prefetch GI
        float2 pgi[2][2][3];
#pragma unroll
        for (int half = 0; half < 2; half++) {
            const size_t gib = ((size_t)(half ? m_b : m_a) * Tsz + t) * (size_t)H3;
#pragma unroll
            for (int j = 0; j < 2; j++) {
                const int hcol = hb + nw * 16 + j * 8 + thr * 2;
#pragma unroll
                for (int g = 0; g < 3; g++)
                    pgi[half][j][g] = *(const float2*)&GI[gib + g * Hsz + hcol];
            }
        }

        float acc[2][3][4];   // [j][g][c]
#pragma unroll
        for (int j = 0; j < 2; j++)
#pragma unroll
            for (int g = 0; g < 3; g++)
#pragma unroll
                for (int c = 0; c < 4; c++) acc[j][g][c] = 0.0f;

        // distance-2 A prefetch (per kp: one uint4 per row = 2 kt groups)
        uint4 pfA[2][2];
        const size_t abase_a = (size_t)m_a * 16;
        const size_t abase_b = (size_t)m_b * 16;
#pragma unroll
        for (int p = 0; p < 2; p++) {
            pfA[p][0] = __ldcg((const uint4*)&Af[(abase_a + p) * 16 + thr * 4]);
            pfA[p][1] = __ldcg((const uint4*)&Af[(abase_b + p) * 16 + thr * 4]);
        }

#pragma unroll 4
        for (int kp = 0; kp < 16; ++kp) {
            const uint4 arA = pfA[kp & 1][0];  // [kt0b0, kt0b1, kt1b0, kt1b1] m_a
            const uint4 arB = pfA[kp & 1][1];  // same for m_b
            if (kp < 14) {
                pfA[kp & 1][0] = __ldcg((const uint4*)&Af[(abase_a + kp + 2) * 16 + thr * 4]);
                pfA[kp & 1][1] = __ldcg((const uint4*)&Af[(abase_b + kp + 2) * 16 + thr * 4]);
            }
            // kt even
#pragma unroll
            for (int g = 0; g < 3; g++) {
                const uint4 bb = *(const uint4*)&Bw[(size_t)(((kp * 2) * 3 + g) * 2 + nw) * 128 + lane * 4];
                mma_bf16(acc[0][g], arA.x, arB.x, arA.y, arB.y, bb.x, bb.y);
                mma_bf16(acc[1][g], arA.x, arB.x, arA.y, arB.y, bb.z, bb.w);
            }
            // kt odd
#pragma unroll
            for (int g = 0; g < 3; g++) {
                const uint4 bb = *(const uint4*)&Bw[(size_t)(((kp * 2 + 1) * 3 + g) * 2 + nw) * 128 + lane * 4];
                mma_bf16(acc[0][g], arA.z, arB.z, arA.w, arB.w, bb.x, bb.y);
                mma_bf16(acc[1][g], arA.z, arB.z, arA.w, arB.w, bb.z, bb.w);
            }
        }

        // epilogue: gates + state update (h fp32 in registers)
#pragma unroll
        for (int half = 0; half < 2; half++) {
            const int m = half ? m_b : m_a;
            const int sl = half ? seq_b : seq_a;
            const int ai = half * 2;
            const size_t bt = (size_t)m * Tsz + t;
#pragma unroll
            for (int j = 0; j < 2; j++) {
                const int hcol = hb + nw * 16 + j * 8 + thr * 2;
                if (t < sl) {
                    const float ghr0 = acc[j][0][ai] + bh[j][0].x;
                    const float ghr1 = acc[j][0][ai + 1] + bh[j][0].y;
                    const float ghz0 = acc[j][1][ai] + bh[j][1].x;
                    const float ghz1 = acc[j][1][ai + 1] + bh[j][1].y;
                    const float ghn0 = acc[j][2][ai] + bh[j][2].x;
                    const float ghn1 = acc[j][2][ai + 1] + bh[j][2].y;
                    const float r0 = __fdividef(1.0f, 1.0f + __expf(-(pgi[half][j][0].x + ghr0)));
                    const float r1 = __fdividef(1.0f, 1.0f + __expf(-(pgi[half][j][0].y + ghr1)));
                    const float z0 = __fdividef(1.0f, 1.0f + __expf(-(pgi[half][j][1].x + ghz0)));
                    const float z1 = __fdividef(1.0f, 1.0f + __expf(-(pgi[half][j][1].y + ghz1)));
                    const float n0v = tanhf(pgi[half][j][2].x + r0 * ghn0);
                    const float n1v = tanhf(pgi[half][j][2].y + r1 * ghn1);
                    const float hn0 = (1.0f - z0) * n0v + z0 * hreg[half][j][0];
                    const float hn1 = (1.0f - z1) * n1v + z1 * hreg[half][j][1];
                    hreg[half][j][0] = hn0;
                    hreg[half][j][1] = hn1;
                    *(float2*)&ffin[bt * (size_t)Hsz + hcol] = make_float2(hn0, hn1);
                } else {
                    *(float2*)&ffin[bt * (size_t)Hsz + hcol] = make_float2(0.0f, 0.0f);
                }
            }
            // one uint2 store: [j0 pack, j1 pack] at kp_g / parity slot
            const size_t ab = ((size_t)m * 16 + kp_g) * 16 + thr * 4 + par_g * 2;
            uint2 st;
            st.x = bf2pack(hreg[half][0][0], hreg[half][0][1]);
            st.y = bf2pack(hreg[half][1][0], hreg[half][1][1]);
            *(uint2*)&Ao[ab] = st;
        }

        // per-m-group barrier (16 blocks)
        if (t < Tsz - 1) {
            __threadfence();
            __syncthreads();
            if (tid == 0) {
                unsigned* ctr = &g_barg[mgrp * 32];
                atomicAdd(ctr, 1u);
                const unsigned target = 16u * (unsigned)(t + 1);
                while (atomicAdd(ctr, 0u) < target) __nanosleep(32);
            }
            __syncthreads();
        }
    }
}

// ---------------- output GEMM: Y = hid @ W2 + b2, PAD-masked ---------------------
__global__ __launch_bounds__(256) void out_gemm_kernel(const float* __restrict__ W2,
                                                       const float* __restrict__ b2,
                                                       const int* __restrict__ seq,
                                                       float* __restrict__ Y) {
    const int m0 = blockIdx.x * 128;
    const int b  = m0 / Tsz;
    const int t0 = m0 % Tsz;
    const int tid = threadIdx.x;
    const int slen = seq[b];
    if (t0 >= slen) {
        float4 pv = make_float4(PADV, PADV, PADV, PADV);
#pragma unroll
        for (int l = 0; l < 8; l++) {
            int idx = tid + l * 256;
            *(float4*)&Y[(size_t)(m0 + (idx >> 4)) * OUTsz + (idx & 15) * 4] = pv;
        }
        return;
    }
    __shared__ float As[32][128];
    __shared__ float Bs[32][64];
    const int tx = tid % 16, ty = tid / 16;
    const int row0 = ty * 8, col0 = tx * 4;
    unsigned long long acc[8][2];
#pragma unroll
    for (int i = 0; i < 8; i++) { acc[i][0] = 0ULL; acc[i][1] = 0ULL; }

    for (int k0 = 0; k0 < FFsz; k0 += 32) {
#pragma unroll
        for (int l = 0; l < 4; l++) {
            int idx = tid + l * 256;
            int r = idx >> 3, c4 = (idx & 7) * 4;
            float4 v = *(const float4*)&g_hid[(size_t)(m0 + r) * FFsz + k0 + c4];
            As[c4 + 0][r] = v.x; As[c4 + 1][r] = v.y;
            As[c4 + 2][r] = v.z; As[c4 + 3][r] = v.w;
        }
#pragma unroll
        for (int l = 0; l < 2; l++) {
            int idx = tid + l * 256;
            int k = idx >> 4, c4 = (idx & 15) * 4;
            *(float4*)&Bs[k][c4] = *(const float4*)&W2[(size_t)(k0 + k) * OUTsz + c4];
        }
        __syncthreads();
#pragma unroll
        for (int k = 0; k < 32; k++) {
            float4 a0 = *(const float4*)&As[k][row0];
            float4 a1 = *(const float4*)&As[k][row0 + 4];
            unsigned long long b0 = *(const unsigned long long*)&Bs[k][col0];
            unsigned long long b1 = *(const unsigned long long*)&Bs[k][col0 + 2];
            float av[8] = {a0.x, a0.y, a0.z, a0.w, a1.x, a1.y, a1.z, a1.w};
#pragma unroll
            for (int i = 0; i < 8; i++) {
                unsigned long long ad = pack2(av[i], av[i]);
                fma2(acc[i][0], ad, b0);
                fma2(acc[i][1], ad, b1);
            }
        }
        __syncthreads();
    }
#pragma unroll
    for (int i = 0; i < 8; i++) {
        int m = m0 + row0 + i;
        int t = t0 + row0 + i;
        float o[4];
        unpack2(acc[i][0], o[0], o[1]);
        unpack2(acc[i][1], o[2], o[3]);
        float4 v;
        if (t < slen) {
            v = make_float4(o[0] + b2[col0 + 0], o[1] + b2[col0 + 1],
                            o[2] + b2[col0 + 2], o[3] + b2[col0 + 3]);
        } else {
            v = make_float4(PADV, PADV, PADV, PADV);
        }
        *(float4*)&Y[(size_t)m * OUTsz + col0] = v;
    }
}

// ---------------- launch ----------------
extern "C" void kernel_launch(void* const* d_in, const int* in_sizes, int n_in,
                              void* d_out, int out_size) {
    (void)in_sizes; (void)n_in; (void)out_size;
    const float* x    = (const float*)d_in[0];
    const int*   seq  = (const int*)d_in[1];
    const float* W_ih = (const float*)d_in[2];
    const float* W_hh = (const float*)d_in[3];
    const float* b_ih = (const float*)d_in[4];
    const float* b_hh = (const float*)d_in[5];
    const float* W1   = (const float*)d_in[6];
    const float* b1   = (const float*)d_in[7];
    const float* W2   = (const float*)d_in[8];
    const float* b2   = (const float*)d_in[9];
    float* Y = (float*)d_out;

    float *pGI = nullptr, *pFF = nullptr, *pHID = nullptr;
    cudaGetSymbolAddress((void**)&pGI, g_GI);
    cudaGetSymbolAddress((void**)&pFF, g_ffin);
    cudaGetSymbolAddress((void**)&pHID, g_hid);

    const int smem_bytes = GW_WORDS * 4;   // 98,304 B
    static bool attr_set = false;
    if (!attr_set) {
        cudaFuncSetAttribute(gru_mma, cudaFuncAttributeMaxDynamicSharedMemorySize,
                             smem_bytes);
        attr_set = true;
    }

    init_kernel<<<(Bsz * 256 + 255) / 256, 256>>>();
    wprep_kernel<<<(16 * 32 * 3 * 2 * 32 + 255) / 256, 256>>>(W_hh);

    // GI = x @ W_ih^T + b_ih   (plain bf16 mma)
    hgemm<Fsz, H3, true, false, true>
        <<<dim3(BT / 128, H3 / 128), 256>>>(x, W_ih, b_ih, pGI, seq);

    gru_mma<<<128, 256, smem_bytes>>>(pGI, b_hh, seq, pFF);

    // HID = relu(ffin @ W1 + b1)   (plain bf16 mma)
    hgemm<Hsz, FFsz, false, true, true>
        <<<dim3(BT / 128, FFsz / 128), 256>>>(pFF, W1, b1, pHID, seq);

    out_gemm_kernel<<<dim3(BT / 128), 256>>>(W2, b2, seq, Y);
}